// round 8
// baseline (speedup 1.0000x reference)
#include <cuda_runtime.h>
#include <math.h>

#define B_  2
#define L_  512
#define H_  128
#define NH_ 2
#define DH_ 64
#define RV_ 257   // REL_VOCAB

// Scratch (allocation-free rule: __device__ globals)
__device__ float g_Q[B_ * L_ * H_];
__device__ float g_K[B_ * L_ * H_];
__device__ float g_V[B_ * L_ * H_];
__device__ float g_O[B_ * L_ * H_];

#define TM 8   // rows per GEMM block (measured-best)

// ---------------------------------------------------------------------------
// Kernel 1: fused QKV projections. grid = (128, 3). blockIdx.y selects matrix.
//   Y = X @ W^T + b  (+ E[pos] for K and V)
// ---------------------------------------------------------------------------
__global__ __launch_bounds__(128) void qkv_kernel(
    const float* __restrict__ query, const float* __restrict__ key,
    const float* __restrict__ value,
    const float* __restrict__ Wq, const float* __restrict__ bq,
    const float* __restrict__ Wk, const float* __restrict__ bk,
    const float* __restrict__ Wv, const float* __restrict__ bv,
    const float* __restrict__ E_PK, const float* __restrict__ E_PV,
    const int* __restrict__ poss)
{
    const int m = blockIdx.y;
    const float *X, *W, *bias, *E;
    float* Y;
    if (m == 0)      { X = query; W = Wq; bias = bq; E = nullptr; Y = g_Q; }
    else if (m == 1) { X = key;   W = Wk; bias = bk; E = E_PK;    Y = g_K; }
    else             { X = value; W = Wv; bias = bv; E = E_PV;    Y = g_V; }

    __shared__ float4 xs[TM][32];   // TM rows x 128 floats

    const int r0 = blockIdx.x * TM;
    const int o  = threadIdx.x;     // output channel 0..127

    const float4* Xv = (const float4*)(X + (size_t)r0 * H_);
    #pragma unroll
    for (int t = 0; t < (TM * 32) / 128; t++)
        ((float4*)xs)[o + t * 128] = Xv[o + t * 128];
    __syncthreads();

    float acc[TM];
    {
        float bb = bias[o];
        #pragma unroll
        for (int rr = 0; rr < TM; rr++) {
            acc[rr] = bb;
            if (E) acc[rr] += E[(size_t)poss[r0 + rr] * H_ + o];
        }
    }

    const float4* w4p = (const float4*)(W + (size_t)o * H_);
    #pragma unroll 4
    for (int c = 0; c < 32; c++) {
        float4 w = w4p[c];
        #pragma unroll
        for (int rr = 0; rr < TM; rr++) {
            float4 x = xs[rr][c];
            acc[rr] = fmaf(w.x, x.x, acc[rr]);
            acc[rr] = fmaf(w.y, x.y, acc[rr]);
            acc[rr] = fmaf(w.z, x.z, acc[rr]);
            acc[rr] = fmaf(w.w, x.w, acc[rr]);
        }
    }

    #pragma unroll
    for (int rr = 0; rr < TM; rr++)
        Y[(size_t)(r0 + rr) * H_ + o] = acc[rr];
}

// ---------------------------------------------------------------------------
// Full 64-dim dot of smem q (float4 broadcast) against a global row.
// ---------------------------------------------------------------------------
__device__ __forceinline__ float dot64(const float4* __restrict__ qs4,
                                       const float* __restrict__ row)
{
    const float4* r4 = (const float4*)row;
    float a0 = 0.f, a1 = 0.f;
    #pragma unroll
    for (int c = 0; c < 16; c += 2) {
        float4 q0 = qs4[c],     k0 = r4[c];
        float4 q1 = qs4[c + 1], k1 = r4[c + 1];
        a0 = fmaf(q0.x, k0.x, a0); a0 = fmaf(q0.y, k0.y, a0);
        a0 = fmaf(q0.z, k0.z, a0); a0 = fmaf(q0.w, k0.w, a0);
        a1 = fmaf(q1.x, k1.x, a1); a1 = fmaf(q1.y, k1.y, a1);
        a1 = fmaf(q1.z, k1.z, a1); a1 = fmaf(q1.w, k1.w, a1);
    }
    return a0 + a1;
}

// ---------------------------------------------------------------------------
// Kernel 2: attention, block per (b,h,i), 256 threads. Shuffle-free dots:
//   rs[r] = q . E_RK[r]                    (thread per r)
//   s[j]  = (q . K_j + rs[idx[j]]) / 8     (thread per j)
//   w     = softmax(s)
//   ws[r] = sum_{j: idx[j]==r} w[j]        (smem histogram)
//   out   = sum_j w[j] V_j + sum_r ws[r] E_RV[r]   (coalesced sweeps)
// ---------------------------------------------------------------------------
__global__ __launch_bounds__(256) void attn_kernel(
    const float* __restrict__ E_RK, const float* __restrict__ E_RV,
    const int* __restrict__ interval)
{
    const int i = L_ - 1 - blockIdx.x;   // long queries first (wave balance)
    const int h = blockIdx.y;
    const int b = blockIdx.z;
    const int tid  = threadIdx.x;
    const int warp = tid >> 5;
    const int lane = tid & 31;
    const int hd = h * DH_;
    const int n = i + 1;                 // causal: keys j in [0, n)

    __shared__ float qs[DH_];
    __shared__ float rs[RV_ + 3];
    __shared__ float ws[RV_ + 3];
    __shared__ float sc[L_];
    __shared__ int   idxs[L_];
    __shared__ float red[8];

    // --- setup: q, interval idx row, zero histogram ---
    if (tid < DH_)
        qs[tid] = g_Q[((size_t)(b * L_ + i)) * H_ + hd + tid];
    {
        const int* iv = interval + ((size_t)(b * L_ + i)) * L_;
        for (int j = tid; j < n; j += 256) idxs[j] = iv[j];
    }
    for (int r = tid; r < RV_; r += 256) ws[r] = 0.f;
    __syncthreads();

    const float4* qs4 = (const float4*)qs;

    // --- phase 1: rs[r] = q . E_RK[r]  (thread per r, no shuffles) ---
    for (int r = tid; r < RV_; r += 256)
        rs[r] = dot64(qs4, E_RK + (size_t)r * H_ + hd);
    __syncthreads();

    // --- phase 2: scores (thread per j, no shuffles) ---
    {
        const float* Kb = g_K + (size_t)b * L_ * H_ + hd;
        for (int j = tid; j < n; j += 256) {
            float p = dot64(qs4, Kb + (size_t)j * H_);
            sc[j] = 0.125f * (p + rs[idxs[j]]);
        }
    }
    __syncthreads();

    // --- phase 3: softmax over sc[0..n) (warp reduce + tiny smem combine) ---
    {
        float m = -INFINITY;
        for (int j = tid; j < n; j += 256) m = fmaxf(m, sc[j]);
        #pragma unroll
        for (int off = 16; off > 0; off >>= 1)
            m = fmaxf(m, __shfl_xor_sync(0xffffffffu, m, off));
        if (lane == 0) red[warp] = m;
        __syncthreads();
        m = fmaxf(fmaxf(fmaxf(red[0], red[1]), fmaxf(red[2], red[3])),
                  fmaxf(fmaxf(red[4], red[5]), fmaxf(red[6], red[7])));

        float s = 0.f;
        for (int j = tid; j < n; j += 256) {
            float e = __expf(sc[j] - m);
            sc[j] = e;
            s += e;
        }
        #pragma unroll
        for (int off = 16; off > 0; off >>= 1)
            s += __shfl_xor_sync(0xffffffffu, s, off);
        __syncthreads();           // red[] reuse
        if (lane == 0) red[warp] = s;
        __syncthreads();
        float tot = (red[0] + red[1]) + (red[2] + red[3]) +
                    (red[4] + red[5]) + (red[6] + red[7]);
        float inv = 1.f / tot;

        // --- phase 4 fused: normalize + histogram ---
        for (int j = tid; j < n; j += 256) {
            float w = sc[j] * inv;
            sc[j] = w;
            atomicAdd(&ws[idxs[j]], w);
        }
    }
    __syncthreads();

    // --- phase 5: out[d] = sum_j w_j V_j[d] + sum_r ws[r] E_RV[r][d] ---
    {
        const int d = tid & 63;
        const int g = tid >> 6;
        const float* Vb = g_V + (size_t)b * L_ * H_ + hd;
        float acc = 0.f;
        for (int j = g; j < n; j += 4)
            acc = fmaf(sc[j], Vb[(size_t)j * H_ + d], acc);
        for (int r = g; r < RV_; r += 4)
            acc = fmaf(ws[r], E_RV[(size_t)r * H_ + hd + d], acc);

        // reuse sc[] region as 256-float reduction buffer (scores are dead)
        __syncthreads();
        sc[g * 64 + d] = acc;
        __syncthreads();
        if (g == 0) {
            float o = sc[d] + sc[64 + d] + sc[128 + d] + sc[192 + d];
            g_O[((size_t)(b * L_ + i)) * H_ + hd + d] = o;
        }
    }
}

// ---------------------------------------------------------------------------
// Kernel 3: output projection: out = O @ Wo^T + bo, NaN -> 0. grid = 128.
// ---------------------------------------------------------------------------
__global__ __launch_bounds__(128) void proj_kernel(
    const float* __restrict__ Wo, const float* __restrict__ bo,
    float* __restrict__ out)
{
    __shared__ float4 xs[TM][32];

    const int r0 = blockIdx.x * TM;
    const int o  = threadIdx.x;

    const float4* Xv = (const float4*)(g_O + (size_t)r0 * H_);
    #pragma unroll
    for (int t = 0; t < (TM * 32) / 128; t++)
        ((float4*)xs)[o + t * 128] = Xv[o + t * 128];
    __syncthreads();

    float acc[TM];
    {
        float bb = bo[o];
        #pragma unroll
        for (int rr = 0; rr < TM; rr++) acc[rr] = bb;
    }

    const float4* w4p = (const float4*)(Wo + (size_t)o * H_);
    #pragma unroll 4
    for (int c = 0; c < 32; c++) {
        float4 w = w4p[c];
        #pragma unroll
        for (int rr = 0; rr < TM; rr++) {
            float4 x = xs[rr][c];
            acc[rr] = fmaf(w.x, x.x, acc[rr]);
            acc[rr] = fmaf(w.y, x.y, acc[rr]);
            acc[rr] = fmaf(w.z, x.z, acc[rr]);
            acc[rr] = fmaf(w.w, x.w, acc[rr]);
        }
    }

    #pragma unroll
    for (int rr = 0; rr < TM; rr++) {
        float v = acc[rr];
        if (isnan(v)) v = 0.f;
        out[(size_t)(r0 + rr) * H_ + o] = v;
    }
}

// ---------------------------------------------------------------------------
extern "C" void kernel_launch(void* const* d_in, const int* in_sizes, int n_in,
                              void* d_out, int out_size)
{
    const float* query    = (const float*)d_in[0];
    const float* key      = (const float*)d_in[1];
    const float* value    = (const float*)d_in[2];
    const float* Wq       = (const float*)d_in[3];
    const float* bq       = (const float*)d_in[4];
    const float* Wk       = (const float*)d_in[5];
    const float* bk       = (const float*)d_in[6];
    const float* Wv       = (const float*)d_in[7];
    const float* bv       = (const float*)d_in[8];
    const float* Wo       = (const float*)d_in[9];
    const float* bo       = (const float*)d_in[10];
    const float* E_PK     = (const float*)d_in[11];
    const float* E_PV     = (const float*)d_in[12];
    const float* E_RK     = (const float*)d_in[13];
    const float* E_RV     = (const float*)d_in[14];
    const int*   poss     = (const int*)d_in[15];
    const int*   interval = (const int*)d_in[16];
    // d_in[17] = attn_mask (exactly tril; causal is hardcoded)

    float* out = (float*)d_out;

    dim3 qgrid((B_ * L_) / TM, 3);
    qkv_kernel<<<qgrid, 128>>>(
        query, key, value, Wq, bq, Wk, bk, Wv, bv, E_PK, E_PV, poss);

    dim3 agrid(L_, NH_, B_);
    attn_kernel<<<agrid, 256>>>(E_RK, E_RV, interval);

    proj_kernel<<<(B_ * L_) / TM, 128>>>(Wo, bo, out);
}

// round 9
// speedup vs baseline: 1.0883x; 1.0883x over previous
#include <cuda_runtime.h>
#include <math.h>

#define B_  2
#define L_  512
#define H_  128
#define NH_ 2
#define DH_ 64
#define RV_ 257   // REL_VOCAB

// Scratch (allocation-free rule: __device__ globals)
__device__ float g_Q[B_ * L_ * H_];
__device__ float g_K[B_ * L_ * H_];
__device__ float g_V[B_ * L_ * H_];
__device__ float g_O[B_ * L_ * H_];

#define TM 8   // rows per GEMM block (measured-best)

// ---------------------------------------------------------------------------
// Kernel 1: fused QKV projections. grid = (128, 3). blockIdx.y selects matrix.
//   Y = X @ W^T + b  (+ E[pos] for K and V)     (unchanged from 98.4us best)
// ---------------------------------------------------------------------------
__global__ __launch_bounds__(128) void qkv_kernel(
    const float* __restrict__ query, const float* __restrict__ key,
    const float* __restrict__ value,
    const float* __restrict__ Wq, const float* __restrict__ bq,
    const float* __restrict__ Wk, const float* __restrict__ bk,
    const float* __restrict__ Wv, const float* __restrict__ bv,
    const float* __restrict__ E_PK, const float* __restrict__ E_PV,
    const int* __restrict__ poss)
{
    const int m = blockIdx.y;
    const float *X, *W, *bias, *E;
    float* Y;
    if (m == 0)      { X = query; W = Wq; bias = bq; E = nullptr; Y = g_Q; }
    else if (m == 1) { X = key;   W = Wk; bias = bk; E = E_PK;    Y = g_K; }
    else             { X = value; W = Wv; bias = bv; E = E_PV;    Y = g_V; }

    __shared__ float4 xs[TM][32];   // TM rows x 128 floats

    const int r0 = blockIdx.x * TM;
    const int o  = threadIdx.x;     // output channel 0..127

    const float4* Xv = (const float4*)(X + (size_t)r0 * H_);
    #pragma unroll
    for (int t = 0; t < (TM * 32) / 128; t++)
        ((float4*)xs)[o + t * 128] = Xv[o + t * 128];
    __syncthreads();

    float acc[TM];
    {
        float bb = bias[o];
        #pragma unroll
        for (int rr = 0; rr < TM; rr++) {
            acc[rr] = bb;
            if (E) acc[rr] += E[(size_t)poss[r0 + rr] * H_ + o];
        }
    }

    const float4* w4p = (const float4*)(W + (size_t)o * H_);
    #pragma unroll 4
    for (int c = 0; c < 32; c++) {
        float4 w = w4p[c];
        #pragma unroll
        for (int rr = 0; rr < TM; rr++) {
            float4 x = xs[rr][c];
            acc[rr] = fmaf(w.x, x.x, acc[rr]);
            acc[rr] = fmaf(w.y, x.y, acc[rr]);
            acc[rr] = fmaf(w.z, x.z, acc[rr]);
            acc[rr] = fmaf(w.w, x.w, acc[rr]);
        }
    }

    #pragma unroll
    for (int rr = 0; rr < TM; rr++)
        Y[(size_t)(r0 + rr) * H_ + o] = acc[rr];
}

// ---------------------------------------------------------------------------
// Kernel 2: attention. Block per (b, h, 4-query tile), 256 threads.
// All global rows staged through a padded smem tile (coalesced float4 LDG,
// conflict-free LDS), reused by the 4 queries. No shuffles in the hot path.
//   rs[q][r] = q_q . E_RK[r]
//   s[q][j]  = (q_q . K_j + rs[q][idx[q][j]]) / 8
//   w        = softmax rowwise
//   ws[q][r] = sum_{j: idx=r} w[q][j]
//   out[q]   = sum_j w V_j + sum_r ws E_RV[r]
// ---------------------------------------------------------------------------
#define QB  4            // queries per block
#define CH  64           // staged rows per chunk
#define PAD 17           // row pitch in float4 (68 floats; 68 % 32 == 4)

__global__ __launch_bounds__(256) void attn_kernel(
    const float* __restrict__ E_RK, const float* __restrict__ E_RV,
    const int* __restrict__ interval)
{
    const int tile = (L_ / QB - 1) - blockIdx.x;  // long queries first
    const int h = blockIdx.y;
    const int b = blockIdx.z;
    const int i0 = tile * QB;
    const int nmax = i0 + QB;

    const int tid  = threadIdx.x;
    const int q    = tid >> 6;       // 0..3   query slot
    const int sub  = tid & 63;       // 0..63  row / dim slot
    const int warp = tid >> 5;
    const int lane = tid & 31;
    const int hd = h * DH_;
    const int nq = i0 + q + 1;       // keys for this thread's query

    __shared__ float4 qs4[QB][16];               // q tile (4 x 64)
    __shared__ float  rs[QB][RV_ + 3];
    __shared__ float  ws[QB][RV_ + 3];
    __shared__ float  sc[QB][L_];
    __shared__ int    idxs[QB][L_];
    __shared__ float4 st4[CH * PAD];             // staging tile 64 x 68 floats
    __shared__ float  red2[8];

    float* st = (float*)st4;

    // ---- phase 0: q tile, interval rows, zero histograms ----
    if (tid < QB * 16) {
        int qq = tid >> 4, c = tid & 15;
        qs4[qq][c] =
            ((const float4*)(g_Q + ((size_t)(b * L_ + i0 + qq)) * H_ + hd))[c];
    }
    #pragma unroll
    for (int qq = 0; qq < QB; qq++) {
        const int* iv = interval + ((size_t)(b * L_ + i0 + qq)) * L_;
        int nqq = i0 + qq + 1;
        for (int j = tid; j < nqq; j += 256) idxs[qq][j] = iv[j];
        for (int r = tid; r < RV_; r += 256) ws[qq][r] = 0.f;
    }
    __syncthreads();

    const float4* qp = qs4[q];

    // ---- phase 1: rs[q][r] = q . E_RK[r] (staged chunks) ----
    for (int r0 = 0; r0 < RV_; r0 += CH) {
        int rows = min(CH, RV_ - r0);
        for (int idx4 = tid; idx4 < rows * 16; idx4 += 256) {
            int rl = idx4 >> 4, c = idx4 & 15;
            st4[rl * PAD + c] =
                ((const float4*)(E_RK + (size_t)(r0 + rl) * H_ + hd))[c];
        }
        __syncthreads();
        if (sub < rows) {
            const float4* kp = &st4[sub * PAD];
            float a0 = 0.f, a1 = 0.f;
            #pragma unroll
            for (int c = 0; c < 16; c += 2) {
                float4 k0 = kp[c], v0 = qp[c];
                float4 k1 = kp[c + 1], v1 = qp[c + 1];
                a0 = fmaf(v0.x, k0.x, a0); a0 = fmaf(v0.y, k0.y, a0);
                a0 = fmaf(v0.z, k0.z, a0); a0 = fmaf(v0.w, k0.w, a0);
                a1 = fmaf(v1.x, k1.x, a1); a1 = fmaf(v1.y, k1.y, a1);
                a1 = fmaf(v1.z, k1.z, a1); a1 = fmaf(v1.w, k1.w, a1);
            }
            rs[q][r0 + sub] = a0 + a1;
        }
        __syncthreads();
    }

    // ---- phase 2: scores (staged K chunks) ----
    {
        const float* Kb = g_K + (size_t)b * L_ * H_ + hd;
        for (int j0 = 0; j0 < nmax; j0 += CH) {
            int rows = min(CH, nmax - j0);
            for (int idx4 = tid; idx4 < rows * 16; idx4 += 256) {
                int rl = idx4 >> 4, c = idx4 & 15;
                st4[rl * PAD + c] =
                    ((const float4*)(Kb + (size_t)(j0 + rl) * H_))[c];
            }
            __syncthreads();
            int j = j0 + sub;
            if (sub < rows && j < nq) {
                const float4* kp = &st4[sub * PAD];
                float a0 = 0.f, a1 = 0.f;
                #pragma unroll
                for (int c = 0; c < 16; c += 2) {
                    float4 k0 = kp[c], v0 = qp[c];
                    float4 k1 = kp[c + 1], v1 = qp[c + 1];
                    a0 = fmaf(v0.x, k0.x, a0); a0 = fmaf(v0.y, k0.y, a0);
                    a0 = fmaf(v0.z, k0.z, a0); a0 = fmaf(v0.w, k0.w, a0);
                    a1 = fmaf(v1.x, k1.x, a1); a1 = fmaf(v1.y, k1.y, a1);
                    a1 = fmaf(v1.z, k1.z, a1); a1 = fmaf(v1.w, k1.w, a1);
                }
                sc[q][j] = 0.125f * (a0 + a1 + rs[q][idxs[q][j]]);
            }
            __syncthreads();
        }
    }

    // ---- phase 3: softmax per query (2 warps each) + histogram ----
    {
        float m = -INFINITY;
        for (int j = sub; j < nq; j += 64) m = fmaxf(m, sc[q][j]);
        #pragma unroll
        for (int off = 16; off > 0; off >>= 1)
            m = fmaxf(m, __shfl_xor_sync(0xffffffffu, m, off));
        if (lane == 0) red2[warp] = m;
        __syncthreads();
        m = fmaxf(red2[2 * q], red2[2 * q + 1]);

        float s = 0.f;
        for (int j = sub; j < nq; j += 64) {
            float e = __expf(sc[q][j] - m);
            sc[q][j] = e;
            s += e;
        }
        #pragma unroll
        for (int off = 16; off > 0; off >>= 1)
            s += __shfl_xor_sync(0xffffffffu, s, off);
        __syncthreads();
        if (lane == 0) red2[warp] = s;
        __syncthreads();
        float inv = 1.f / (red2[2 * q] + red2[2 * q + 1]);

        for (int j = sub; j < nq; j += 64) {
            float w = sc[q][j] * inv;
            sc[q][j] = w;
            atomicAdd(&ws[q][idxs[q][j]], w);
        }
    }
    __syncthreads();

    // ---- phase 5: output (staged V chunks, then staged E_RV chunks) ----
    {
        const int d = sub;
        float acc = 0.f;

        const float* Vb = g_V + (size_t)b * L_ * H_ + hd;
        for (int j0 = 0; j0 < nmax; j0 += CH) {
            int rows = min(CH, nmax - j0);
            for (int idx4 = tid; idx4 < rows * 16; idx4 += 256) {
                int rl = idx4 >> 4, c = idx4 & 15;
                st4[rl * PAD + c] =
                    ((const float4*)(Vb + (size_t)(j0 + rl) * H_))[c];
            }
            __syncthreads();
            int jend = nq - j0;
            if (jend > rows) jend = rows;
            const float4* wp = (const float4*)&sc[q][j0];
            int jl = 0;
            for (; jl + 4 <= jend; jl += 4) {
                float4 w = wp[jl >> 2];
                acc = fmaf(w.x, st[(jl + 0) * (4 * PAD) + d], acc);
                acc = fmaf(w.y, st[(jl + 1) * (4 * PAD) + d], acc);
                acc = fmaf(w.z, st[(jl + 2) * (4 * PAD) + d], acc);
                acc = fmaf(w.w, st[(jl + 3) * (4 * PAD) + d], acc);
            }
            for (; jl < jend; jl++)
                acc = fmaf(sc[q][j0 + jl], st[jl * (4 * PAD) + d], acc);
            __syncthreads();
        }

        for (int r0 = 0; r0 < RV_; r0 += CH) {
            int rows = min(CH, RV_ - r0);
            for (int idx4 = tid; idx4 < rows * 16; idx4 += 256) {
                int rl = idx4 >> 4, c = idx4 & 15;
                st4[rl * PAD + c] =
                    ((const float4*)(E_RV + (size_t)(r0 + rl) * H_ + hd))[c];
            }
            __syncthreads();
            const float4* wp = (const float4*)&ws[q][r0];
            int rl = 0;
            for (; rl + 4 <= rows; rl += 4) {
                float4 w = wp[rl >> 2];
                acc = fmaf(w.x, st[(rl + 0) * (4 * PAD) + d], acc);
                acc = fmaf(w.y, st[(rl + 1) * (4 * PAD) + d], acc);
                acc = fmaf(w.z, st[(rl + 2) * (4 * PAD) + d], acc);
                acc = fmaf(w.w, st[(rl + 3) * (4 * PAD) + d], acc);
            }
            for (; rl < rows; rl++)
                acc = fmaf(ws[q][r0 + rl], st[rl * (4 * PAD) + d], acc);
            __syncthreads();
        }

        g_O[((size_t)(b * L_ + i0 + q)) * H_ + hd + d] = acc;
    }
}

// ---------------------------------------------------------------------------
// Kernel 3: output projection: out = O @ Wo^T + bo, NaN -> 0. grid = 128.
// ---------------------------------------------------------------------------
__global__ __launch_bounds__(128) void proj_kernel(
    const float* __restrict__ Wo, const float* __restrict__ bo,
    float* __restrict__ out)
{
    __shared__ float4 xs[TM][32];

    const int r0 = blockIdx.x * TM;
    const int o  = threadIdx.x;

    const float4* Xv = (const float4*)(g_O + (size_t)r0 * H_);
    #pragma unroll
    for (int t = 0; t < (TM * 32) / 128; t++)
        ((float4*)xs)[o + t * 128] = Xv[o + t * 128];
    __syncthreads();

    float acc[TM];
    {
        float bb = bo[o];
        #pragma unroll
        for (int rr = 0; rr < TM; rr++) acc[rr] = bb;
    }

    const float4* w4p = (const float4*)(Wo + (size_t)o * H_);
    #pragma unroll 4
    for (int c = 0; c < 32; c++) {
        float4 w = w4p[c];
        #pragma unroll
        for (int rr = 0; rr < TM; rr++) {
            float4 x = xs[rr][c];
            acc[rr] = fmaf(w.x, x.x, acc[rr]);
            acc[rr] = fmaf(w.y, x.y, acc[rr]);
            acc[rr] = fmaf(w.z, x.z, acc[rr]);
            acc[rr] = fmaf(w.w, x.w, acc[rr]);
        }
    }

    #pragma unroll
    for (int rr = 0; rr < TM; rr++) {
        float v = acc[rr];
        if (isnan(v)) v = 0.f;
        out[(size_t)(r0 + rr) * H_ + o] = v;
    }
}

// ---------------------------------------------------------------------------
extern "C" void kernel_launch(void* const* d_in, const int* in_sizes, int n_in,
                              void* d_out, int out_size)
{
    const float* query    = (const float*)d_in[0];
    const float* key      = (const float*)d_in[1];
    const float* value    = (const float*)d_in[2];
    const float* Wq       = (const float*)d_in[3];
    const float* bq       = (const float*)d_in[4];
    const float* Wk       = (const float*)d_in[5];
    const float* bk       = (const float*)d_in[6];
    const float* Wv       = (const float*)d_in[7];
    const float* bv       = (const float*)d_in[8];
    const float* Wo       = (const float*)d_in[9];
    const float* bo       = (const float*)d_in[10];
    const float* E_PK     = (const float*)d_in[11];
    const float* E_PV     = (const float*)d_in[12];
    const float* E_RK     = (const float*)d_in[13];
    const float* E_RV     = (const float*)d_in[14];
    const int*   poss     = (const int*)d_in[15];
    const int*   interval = (const int*)d_in[16];
    // d_in[17] = attn_mask (exactly tril; causal is hardcoded)

    float* out = (float*)d_out;

    dim3 qgrid((B_ * L_) / TM, 3);
    qkv_kernel<<<qgrid, 128>>>(
        query, key, value, Wq, bq, Wk, bk, Wv, bv, E_PK, E_PV, poss);

    dim3 agrid(L_ / QB, NH_, B_);
    attn_kernel<<<agrid, 256>>>(E_RK, E_RV, interval);

    proj_kernel<<<(B_ * L_) / TM, 128>>>(Wo, bo, out);
}

// round 10
// speedup vs baseline: 2.1675x; 1.9916x over previous
#include <cuda_runtime.h>
#include <math.h>

#define B_  2
#define L_  512
#define H_  128
#define NH_ 2
#define DH_ 64
#define RV_ 257   // REL_VOCAB
#define SP  512   // score row pitch
#define RVP 320   // rel-vocab row pitch (5*64)
#define BH_ (B_ * NH_)

// Scratch (allocation-free rule: __device__ globals)
__device__ float g_Q[B_ * L_ * H_];   // pre-scaled by 0.125
__device__ float g_K[B_ * L_ * H_];
__device__ float g_V[B_ * L_ * H_];
__device__ float g_O[B_ * L_ * H_];
__device__ float g_S[BH_ * L_ * SP];    // scores, then softmax weights (in place)
__device__ float g_RS[BH_ * L_ * RVP];  // q . E_RK[r]
__device__ float g_WS[BH_ * L_ * RVP];  // weight histogram over rel vocab

#define TM 8   // rows per GEMM block (measured-best for qkv/proj)

// ---------------------------------------------------------------------------
// Kernel 1: fused QKV projections (unchanged structure; Q scaled by 0.125).
// ---------------------------------------------------------------------------
__global__ __launch_bounds__(128) void qkv_kernel(
    const float* __restrict__ query, const float* __restrict__ key,
    const float* __restrict__ value,
    const float* __restrict__ Wq, const float* __restrict__ bq,
    const float* __restrict__ Wk, const float* __restrict__ bk,
    const float* __restrict__ Wv, const float* __restrict__ bv,
    const float* __restrict__ E_PK, const float* __restrict__ E_PV,
    const int* __restrict__ poss)
{
    const int m = blockIdx.y;
    const float *X, *W, *bias, *E;
    float* Y;
    if (m == 0)      { X = query; W = Wq; bias = bq; E = nullptr; Y = g_Q; }
    else if (m == 1) { X = key;   W = Wk; bias = bk; E = E_PK;    Y = g_K; }
    else             { X = value; W = Wv; bias = bv; E = E_PV;    Y = g_V; }

    __shared__ float4 xs[TM][32];

    const int r0 = blockIdx.x * TM;
    const int o  = threadIdx.x;

    const float4* Xv = (const float4*)(X + (size_t)r0 * H_);
    #pragma unroll
    for (int t = 0; t < (TM * 32) / 128; t++)
        ((float4*)xs)[o + t * 128] = Xv[o + t * 128];
    __syncthreads();

    float acc[TM];
    {
        float bb = bias[o];
        #pragma unroll
        for (int rr = 0; rr < TM; rr++) {
            acc[rr] = bb;
            if (E) acc[rr] += E[(size_t)poss[r0 + rr] * H_ + o];
        }
    }

    const float4* w4p = (const float4*)(W + (size_t)o * H_);
    #pragma unroll 4
    for (int c = 0; c < 32; c++) {
        float4 w = w4p[c];
        #pragma unroll
        for (int rr = 0; rr < TM; rr++) {
            float4 x = xs[rr][c];
            acc[rr] = fmaf(w.x, x.x, acc[rr]);
            acc[rr] = fmaf(w.y, x.y, acc[rr]);
            acc[rr] = fmaf(w.z, x.z, acc[rr]);
            acc[rr] = fmaf(w.w, x.w, acc[rr]);
        }
    }

    const float scale = (m == 0) ? 0.125f : 1.0f;   // fold 1/sqrt(DH) into Q
    #pragma unroll
    for (int rr = 0; rr < TM; rr++)
        Y[(size_t)(r0 + rr) * H_ + o] = acc[rr] * scale;
}

// ---------------------------------------------------------------------------
// Kernel A: score GEMMs. grid = (8, 13, 4).
//   blockIdx.y < 8 : S tile  (it, jt) — causal: skip jt > it
//   blockIdx.y >= 8: RS tile (it, rt=y-8), rt < 5
// 256 threads, 64x64x64 tile, 4x4 micro-tile per thread.
// ---------------------------------------------------------------------------
__global__ __launch_bounds__(256) void score_gemm(const float* __restrict__ E_RK)
{
    const int it = blockIdx.x;
    const int yy = blockIdx.y;
    const int bh = blockIdx.z;
    const bool smode = (yy < 8);
    const int jt = smode ? yy : (yy - 8);
    if (smode && jt > it) return;

    const int b = bh >> 1, h = bh & 1, hd = h * DH_;
    const int i0 = it * 64;
    const int j0 = jt * 64;

    __shared__ float As[64 * 68];
    __shared__ float Bs[64 * 68];

    const int tid = threadIdx.x;

    // staging: natural layout [row][k], coalesced float4 loads, aligned stores
    const float* Asrc = g_Q + ((size_t)(b * L_ + i0)) * H_ + hd;
    #pragma unroll
    for (int p = 0; p < 4; p++) {
        int f = tid + 256 * p;
        int row = f >> 4, c4 = f & 15;
        float4 va = ((const float4*)(Asrc + (size_t)row * H_))[c4];
        *(float4*)(As + row * 68 + 4 * c4) = va;
        float4 vb;
        if (smode) {
            vb = ((const float4*)(g_K + ((size_t)(b * L_ + j0 + row)) * H_ + hd))[c4];
        } else {
            int r = j0 + row;
            vb = (r < RV_)
               ? ((const float4*)(E_RK + (size_t)r * H_ + hd))[c4]
               : make_float4(0.f, 0.f, 0.f, 0.f);
        }
        *(float4*)(Bs + row * 68 + 4 * c4) = vb;
    }
    __syncthreads();

    const int tx = tid & 15, ty = tid >> 4;
    float acc[4][4];
    #pragma unroll
    for (int ii = 0; ii < 4; ii++)
        #pragma unroll
        for (int jj = 0; jj < 4; jj++) acc[ii][jj] = 0.f;

    #pragma unroll 4
    for (int kc = 0; kc < 16; kc++) {
        float4 a[4], bb[4];
        #pragma unroll
        for (int u = 0; u < 4; u++) {
            a[u]  = *(const float4*)(As + (4 * ty + u) * 68 + 4 * kc);
            bb[u] = *(const float4*)(Bs + (4 * tx + u) * 68 + 4 * kc);
        }
        #pragma unroll
        for (int ii = 0; ii < 4; ii++)
            #pragma unroll
            for (int jj = 0; jj < 4; jj++) {
                acc[ii][jj] = fmaf(a[ii].x, bb[jj].x, acc[ii][jj]);
                acc[ii][jj] = fmaf(a[ii].y, bb[jj].y, acc[ii][jj]);
                acc[ii][jj] = fmaf(a[ii].z, bb[jj].z, acc[ii][jj]);
                acc[ii][jj] = fmaf(a[ii].w, bb[jj].w, acc[ii][jj]);
            }
    }

    #pragma unroll
    for (int ii = 0; ii < 4; ii++) {
        int gi = i0 + 4 * ty + ii;
        float4 v = make_float4(acc[ii][0], acc[ii][1], acc[ii][2], acc[ii][3]);
        if (smode)
            *(float4*)(g_S + ((size_t)bh * L_ + gi) * SP + j0 + 4 * tx) = v;
        else
            *(float4*)(g_RS + ((size_t)bh * L_ + gi) * RVP + j0 + 4 * tx) = v;
    }
}

// ---------------------------------------------------------------------------
// Kernel B: softmax + rel lookup + histogram. Block per (i, h, b), 256 thr.
//   s[j] = S[i][j] + RS[i][idx[j]]  (Q pre-scaled)
//   w = softmax(s); write w over S (zero-padded to tile edge)
//   WS[i][r] = sum of w with idx==r; zero O row for kernel C's atomics.
// ---------------------------------------------------------------------------
__global__ __launch_bounds__(256) void softmax_kernel(const int* __restrict__ interval)
{
    const int i = blockIdx.x;
    const int h = blockIdx.y;
    const int b = blockIdx.z;
    const int bh = b * NH_ + h;
    const int tid = threadIdx.x;
    const int warp = tid >> 5, lane = tid & 31;
    const int n = i + 1;
    const int jpad = ((i >> 6) + 1) * 64;

    __shared__ float rsr[RV_];
    __shared__ float ws[RVP];
    __shared__ float sc[L_];
    __shared__ int   idxs[L_];
    __shared__ float red[8];

    const float* RSrow = g_RS + ((size_t)bh * L_ + i) * RVP;
    for (int r = tid; r < RV_; r += 256) rsr[r] = RSrow[r];
    for (int r = tid; r < RVP; r += 256) ws[r] = 0.f;
    {
        const int* iv = interval + ((size_t)(b * L_ + i)) * L_;
        for (int j = tid; j < n; j += 256) idxs[j] = iv[j];
    }
    // zero this row's output slice for kernel C's atomic accumulation
    if (tid < DH_)
        g_O[((size_t)(b * L_ + i)) * H_ + h * DH_ + tid] = 0.f;
    __syncthreads();

    float* Srow = g_S + ((size_t)bh * L_ + i) * SP;

    float m = -INFINITY;
    for (int j = tid; j < n; j += 256) {
        float s = Srow[j] + rsr[idxs[j]];
        sc[j] = s;
        m = fmaxf(m, s);
    }
    #pragma unroll
    for (int off = 16; off > 0; off >>= 1)
        m = fmaxf(m, __shfl_xor_sync(0xffffffffu, m, off));
    if (lane == 0) red[warp] = m;
    __syncthreads();
    m = fmaxf(fmaxf(fmaxf(red[0], red[1]), fmaxf(red[2], red[3])),
              fmaxf(fmaxf(red[4], red[5]), fmaxf(red[6], red[7])));

    float s = 0.f;
    for (int j = tid; j < n; j += 256) {
        float e = __expf(sc[j] - m);
        sc[j] = e;
        s += e;
    }
    #pragma unroll
    for (int off = 16; off > 0; off >>= 1)
        s += __shfl_xor_sync(0xffffffffu, s, off);
    __syncthreads();
    if (lane == 0) red[warp] = s;
    __syncthreads();
    float inv = 1.f / ((red[0] + red[1]) + (red[2] + red[3]) +
                       (red[4] + red[5]) + (red[6] + red[7]));

    for (int j = tid; j < n; j += 256) {
        float w = sc[j] * inv;
        Srow[j] = w;
        atomicAdd(&ws[idxs[j]], w);
    }
    for (int j = n + tid; j < jpad; j += 256) Srow[j] = 0.f;
    __syncthreads();

    float* WSrow = g_WS + ((size_t)bh * L_ + i) * RVP;
    for (int r = tid; r < RVP; r += 256) WSrow[r] = ws[r];
}

// ---------------------------------------------------------------------------
// Kernel C: output GEMMs, atomic split-k. grid = (8, 13, 4).
//   y < 8 : O[i0..][d] += W[i][j0+k] * V[j0+k][d]    (skip jt > it)
//   y >= 8: O[i0..][d] += WS[i][r0+k] * E_RV[r0+k][d]
// ---------------------------------------------------------------------------
__global__ __launch_bounds__(256) void out_gemm(const float* __restrict__ E_RV)
{
    const int it = blockIdx.x;
    const int yy = blockIdx.y;
    const int bh = blockIdx.z;
    const bool smode = (yy < 8);
    const int jt = smode ? yy : (yy - 8);
    if (smode && jt > it) return;

    const int b = bh >> 1, h = bh & 1, hd = h * DH_;
    const int i0 = it * 64;
    const int k0 = jt * 64;

    __shared__ float Ws[64 * 68];
    __shared__ float Vs[64 * 68];

    const int tid = threadIdx.x;

    #pragma unroll
    for (int p = 0; p < 4; p++) {
        int f = tid + 256 * p;
        int row = f >> 4, c4 = f & 15;
        float4 vw, vv;
        if (smode) {
            vw = *(const float4*)(g_S + ((size_t)bh * L_ + i0 + row) * SP + k0 + 4 * c4);
            vv = ((const float4*)(g_V + ((size_t)(b * L_ + k0 + row)) * H_ + hd))[c4];
        } else {
            vw = *(const float4*)(g_WS + ((size_t)bh * L_ + i0 + row) * RVP + k0 + 4 * c4);
            int r = k0 + row;
            vv = (r < RV_)
               ? ((const float4*)(E_RV + (size_t)r * H_ + hd))[c4]
               : make_float4(0.f, 0.f, 0.f, 0.f);
        }
        *(float4*)(Ws + row * 68 + 4 * c4) = vw;
        *(float4*)(Vs + row * 68 + 4 * c4) = vv;
    }
    __syncthreads();

    const int tx = tid & 15, ty = tid >> 4;
    float acc[4][4];
    #pragma unroll
    for (int ii = 0; ii < 4; ii++)
        #pragma unroll
        for (int jj = 0; jj < 4; jj++) acc[ii][jj] = 0.f;

    #pragma unroll 8
    for (int k = 0; k < 64; k++) {
        float4 bv = *(const float4*)(Vs + k * 68 + 4 * tx);
        float a0 = Ws[(4 * ty + 0) * 68 + k];
        float a1 = Ws[(4 * ty + 1) * 68 + k];
        float a2 = Ws[(4 * ty + 2) * 68 + k];
        float a3 = Ws[(4 * ty + 3) * 68 + k];
        acc[0][0] = fmaf(a0, bv.x, acc[0][0]); acc[0][1] = fmaf(a0, bv.y, acc[0][1]);
        acc[0][2] = fmaf(a0, bv.z, acc[0][2]); acc[0][3] = fmaf(a0, bv.w, acc[0][3]);
        acc[1][0] = fmaf(a1, bv.x, acc[1][0]); acc[1][1] = fmaf(a1, bv.y, acc[1][1]);
        acc[1][2] = fmaf(a1, bv.z, acc[1][2]); acc[1][3] = fmaf(a1, bv.w, acc[1][3]);
        acc[2][0] = fmaf(a2, bv.x, acc[2][0]); acc[2][1] = fmaf(a2, bv.y, acc[2][1]);
        acc[2][2] = fmaf(a2, bv.z, acc[2][2]); acc[2][3] = fmaf(a2, bv.w, acc[2][3]);
        acc[3][0] = fmaf(a3, bv.x, acc[3][0]); acc[3][1] = fmaf(a3, bv.y, acc[3][1]);
        acc[3][2] = fmaf(a3, bv.z, acc[3][2]); acc[3][3] = fmaf(a3, bv.w, acc[3][3]);
    }

    #pragma unroll
    for (int ii = 0; ii < 4; ii++) {
        float* orow = g_O + ((size_t)(b * L_ + i0 + 4 * ty + ii)) * H_ + hd + 4 * tx;
        #pragma unroll
        for (int jj = 0; jj < 4; jj++)
            atomicAdd(orow + jj, acc[ii][jj]);
    }
}

// ---------------------------------------------------------------------------
// Kernel 3: output projection: out = O @ Wo^T + bo, NaN -> 0. grid = 128.
// ---------------------------------------------------------------------------
__global__ __launch_bounds__(128) void proj_kernel(
    const float* __restrict__ Wo, const float* __restrict__ bo,
    float* __restrict__ out)
{
    __shared__ float4 xs[TM][32];

    const int r0 = blockIdx.x * TM;
    const int o  = threadIdx.x;

    const float4* Xv = (const float4*)(g_O + (size_t)r0 * H_);
    #pragma unroll
    for (int t = 0; t < (TM * 32) / 128; t++)
        ((float4*)xs)[o + t * 128] = Xv[o + t * 128];
    __syncthreads();

    float acc[TM];
    {
        float bb = bo[o];
        #pragma unroll
        for (int rr = 0; rr < TM; rr++) acc[rr] = bb;
    }

    const float4* w4p = (const float4*)(Wo + (size_t)o * H_);
    #pragma unroll 4
    for (int c = 0; c < 32; c++) {
        float4 w = w4p[c];
        #pragma unroll
        for (int rr = 0; rr < TM; rr++) {
            float4 x = xs[rr][c];
            acc[rr] = fmaf(w.x, x.x, acc[rr]);
            acc[rr] = fmaf(w.y, x.y, acc[rr]);
            acc[rr] = fmaf(w.z, x.z, acc[rr]);
            acc[rr] = fmaf(w.w, x.w, acc[rr]);
        }
    }

    #pragma unroll
    for (int rr = 0; rr < TM; rr++) {
        float v = acc[rr];
        if (isnan(v)) v = 0.f;
        out[(size_t)(r0 + rr) * H_ + o] = v;
    }
}

// ---------------------------------------------------------------------------
extern "C" void kernel_launch(void* const* d_in, const int* in_sizes, int n_in,
                              void* d_out, int out_size)
{
    const float* query    = (const float*)d_in[0];
    const float* key      = (const float*)d_in[1];
    const float* value    = (const float*)d_in[2];
    const float* Wq       = (const float*)d_in[3];
    const float* bq       = (const float*)d_in[4];
    const float* Wk       = (const float*)d_in[5];
    const float* bk       = (const float*)d_in[6];
    const float* Wv       = (const float*)d_in[7];
    const float* bv       = (const float*)d_in[8];
    const float* Wo       = (const float*)d_in[9];
    const float* bo       = (const float*)d_in[10];
    const float* E_PK     = (const float*)d_in[11];
    const float* E_PV     = (const float*)d_in[12];
    const float* E_RK     = (const float*)d_in[13];
    const float* E_RV     = (const float*)d_in[14];
    const int*   poss     = (const int*)d_in[15];
    const int*   interval = (const int*)d_in[16];
    // d_in[17] = attn_mask (exactly tril; causal is hardcoded)

    float* out = (float*)d_out;

    dim3 qgrid((B_ * L_) / TM, 3);
    qkv_kernel<<<qgrid, 128>>>(
        query, key, value, Wq, bq, Wk, bk, Wv, bv, E_PK, E_PV, poss);

    dim3 ggrid(8, 13, BH_);
    score_gemm<<<ggrid, 256>>>(E_RK);

    dim3 sgrid(L_, NH_, B_);
    softmax_kernel<<<sgrid, 256>>>(interval);

    out_gemm<<<ggrid, 256>>>(E_RV);

    proj_kernel<<<(B_ * L_) / TM, 128>>>(Wo, bo, out);
}